// round 10
// baseline (speedup 1.0000x reference)
#include <cuda_runtime.h>
#include <cuda_bf16.h>

// x:    [B=64, C=64, S=8192] float32
// mask: [B=64, S=8192] int32
// out:  patches [64, 512, 1024] float32  followed by  padding_mask [64, 512] float32
//
// patches[b, p, c*16 + j] = x[b, c, p*16 + j]   (stride == patch -> pure permutation)
// padding_mask[b, p] = (sum(mask[b, p*16 : p*16+16]) >= 8) ? 1.0f : 0.0f
//
// Best-known config (R9: 35.4us kernel = 7.65 TB/s combined = ~96% of HBM spec):
//   - flat grid, 256-thread blocks, ILP=4 (four independent LDG.128 then 4 STG.128)
//   - 128 latency-bound mask blocks FIRST so their latency hides under the
//     8192 streaming permute blocks (no partial-wave tail)
// This round: strength-reduce the source index — the 4 ILP indices within a
// block differ only by p -> p+1, i.e. src + 4k in float4 units. One address
// computation instead of four. Expected neutral (issue=7%): locking the floor.

#define B       64
#define C       64
#define S       8192
#define NP      512                       // n_patches
#define CP      1024                      // C * PATCH
#define TOTAL_OUT_F4     (B * NP * CP / 4)       // 8388608
#define F4_PER_BLOCK     1024                    // 256 threads x 4
#define PERMUTE_BLOCKS   (TOTAL_OUT_F4 / F4_PER_BLOCK)  // 8192
#define MASK_THREADS     (B * NP)                // 32768
#define MASK_BLOCKS      ((MASK_THREADS + 255) / 256)   // 128

__global__ void __launch_bounds__(256)
fused_patch_kernel(const float4* __restrict__ x4,
                   const int4* __restrict__ m4,
                   float4* __restrict__ out4,
                   float* __restrict__ pm) {
    int blk = blockIdx.x;
    if (blk >= MASK_BLOCKS) {
        // ---- permute: 4 independent LDG.128 then 4 STG.128, fully coalesced ----
        int base = (blk - MASK_BLOCKS) * F4_PER_BLOCK + threadIdx.x;
        // decompose once: the k-th ILP element (base + k*256) only increments p,
        // i.e. source float4 index advances by 4 per k.
        int b  = base >> 17;                  // / 131072 (f4 per batch)
        int r  = base & ((NP * CP / 4) - 1);
        int p  = r >> 8;                      // / 256
        int r2 = r & 255;
        int c  = r2 >> 2;                     // / 4
        int j4 = r2 & 3;
        int src0 = ((b << 6) + c) * (S / 4) + (p << 2) + j4;

        float4 v[4];
        #pragma unroll
        for (int k = 0; k < 4; k++)
            v[k] = x4[src0 + 4 * k];
        #pragma unroll
        for (int k = 0; k < 4; k++)
            out4[base + k * 256] = v[k];
    } else {
        // ---- mask: one (b,p) per thread; scheduled first, hides under permute ----
        int t = blk * 256 + threadIdx.x;
        int b = t >> 9;                       // / 512
        int p = t & (NP - 1);
        int mbase = (b * S + p * 16) >> 2;
        int s = 0;
        #pragma unroll
        for (int k = 0; k < 4; k++) {
            int4 m = m4[mbase + k];
            s += m.x + m.y + m.z + m.w;
        }
        pm[t] = (s >= 8) ? 1.0f : 0.0f;
    }
}

extern "C" void kernel_launch(void* const* d_in, const int* in_sizes, int n_in,
                              void* d_out, int out_size) {
    const float4* x4 = (const float4*)d_in[0];
    const int4*   m4 = (const int4*)d_in[1];
    float* out = (float*)d_out;
    float* pm  = out + (size_t)B * NP * CP;

    fused_patch_kernel<<<MASK_BLOCKS + PERMUTE_BLOCKS, 256>>>(
        x4, m4, (float4*)out, pm);
}